// round 12
// baseline (speedup 1.0000x reference)
#include <cuda_runtime.h>
#include <math.h>
#include <cstdint>

#define DIM 512
#define PI_F 3.14159265358979f   // rounds to 3.14159274f == f32(np.float64 PI)
#define BATCH 64
#define ROWS_PT 4                 // rows per tile
#define TILES   2                 // tiles per block (pipelined)
#define TILE_FLOATS (ROWS_PT * DIM * 3)
#define TILE_BYTES  (TILE_FLOATS * 4)       // 24576
#define SMEM_BYTES  (TILES * TILE_BYTES)    // 49152

// scratch for per-image matrices (allocation-free rule: __device__ global)
__device__ float g_M[BATCH * 6];

// ============================================================================
// Bit-exact replication of glibc (aarch64) sinf/cosf — numerics frozen (R6).
// ============================================================================

__device__ __constant__ double GSIGN[4] = {1.0, -1.0, -1.0, 1.0};

struct SCPoly { double c0, c1, c2, c3, c4, s1, s2, s3; };

__device__ __constant__ SCPoly GTAB[2] = {
    {  0x1p0,
      -0x1.ffffffd0c621cp-2,
       0x1.55553e1068f19p-5,
      -0x1.6c087e89a359dp-10,
       0x1.99343027bf8c3p-16,
      -0x1.555545995a603p-3,
       0x1.1107605230bc4p-7,
      -0x1.994eb3774cf24p-13 },
    { -0x1p0,
       0x1.ffffffd0c621cp-2,
      -0x1.55553e1068f19p-5,
       0x1.6c087e89a359dp-10,
      -0x1.99343027bf8c3p-16,
       0x1.555545995a603p-3,
      -0x1.1107605230bc4p-7,
       0x1.994eb3774cf24p-13 }
};

__device__ __constant__ double G_HPI_INV = 0x1.45F306DC9C883p-1;  // 2/pi
__device__ __constant__ double G_HPI     = 0x1.921FB54442D18p0;   // pi/2

__device__ __forceinline__ unsigned abstop12(float x) {
    return (__float_as_uint(x) >> 20) & 0x7ff;
}

__device__ __forceinline__ double g_sinf_poly(double x, double x2, const SCPoly* p, int n) {
    if ((n & 1) == 0) {
        double x3 = x * x2;
        double s1 = fma(x2, p->s3, p->s2);
        double x7 = x3 * x2;
        double s  = fma(x3, p->s1, x);
        return fma(x7, s1, s);
    } else {
        double x4 = x2 * x2;
        double c2 = fma(x2, p->c4, p->c3);
        double c1 = fma(x2, p->c1, p->c0);
        double x6 = x4 * x2;
        double c  = fma(x4, p->c2, c1);
        return fma(x6, c2, c);
    }
}

__device__ __forceinline__ double g_reduce_fast(double x, int* np) {
    double r = x * G_HPI_INV;
    *np = __double2int_rn(r);
    double rr = rint(r);
    return fma(rr, -G_HPI, x);
}

__device__ float glibc_sinf(float y) {
    unsigned t = abstop12(y);
    if (t < 0x3f4u) {
        double x = (double)y;
        double s = x * x;
        if (t < 0x398u)
            return y;
        return (float)g_sinf_poly(x, s, &GTAB[0], 0);
    } else {
        double x = (double)y;
        int n;
        x = g_reduce_fast(x, &n);
        double s = GSIGN[n & 3];
        const SCPoly* p = (n & 2) ? &GTAB[1] : &GTAB[0];
        return (float)g_sinf_poly(x * s, x * x, p, n);
    }
}

__device__ float glibc_cosf(float y) {
    unsigned t = abstop12(y);
    if (t < 0x3f4u) {
        double x = (double)y;
        double x2 = x * x;
        if (t < 0x398u)
            return 1.0f;
        return (float)g_sinf_poly(x, x2, &GTAB[0], 1);
    } else {
        double x = (double)y;
        int n;
        x = g_reduce_fast(x, &n);
        double s = GSIGN[(n + 1) & 3];
        const SCPoly* p = ((n + 1) & 2) ? &GTAB[1] : &GTAB[0];
        return (float)g_sinf_poly(x * s, x * x, p, n ^ 1);
    }
}

// ============================================================================

__global__ void matrix_kernel(
    const float* __restrict__ rot_n,
    const float* __restrict__ shr_n,
    const float* __restrict__ hz_n,
    const float* __restrict__ wz_n,
    const float* __restrict__ hs_n,
    const float* __restrict__ ws_n)
{
    const int b = threadIdx.x;
    if (b >= BATCH) return;

    float rotation = __fmul_rn(15.0f, rot_n[b]);
    float shear    = __fmul_rn(5.0f,  shr_n[b]);
    float h_zoom   = __fadd_rn(1.0f, __fdiv_rn(hz_n[b], 10.0f));
    float w_zoom   = __fadd_rn(1.0f, __fdiv_rn(wz_n[b], 10.0f));
    float h_shift  = __fmul_rn(16.0f, hs_n[b]);
    float w_shift  = __fmul_rn(16.0f, ws_n[b]);

    float rot = __fdiv_rn(__fmul_rn(PI_F, rotation), 180.0f);
    float shr = __fdiv_rn(__fmul_rn(PI_F, shear), 180.0f);
    float c1 = glibc_cosf(rot), s1 = glibc_sinf(rot);
    float c2 = glibc_cosf(shr), s2 = glibc_sinf(shr);

    // A = rot_m @ shear_m  (fma-ascending — frozen)
    float a00 = c1;
    float a01 = __fmaf_rn(s1, c2, __fmul_rn(c1, s2));
    float a10 = -s1;
    float a11 = __fmaf_rn(c1, c2, __fmul_rn(-s1, s2));

    // B = zoom_m @ shift_m
    float izh = __fdiv_rn(1.0f, h_zoom);
    float izw = __fdiv_rn(1.0f, w_zoom);
    float b00 = izh;
    float b02 = __fmul_rn(izh, h_shift);
    float b11 = izw;
    float b12 = __fmul_rn(izw, w_shift);

    // M = A @ B
    g_M[b * 6 + 0] = __fmul_rn(a00, b00);
    g_M[b * 6 + 1] = __fmul_rn(a01, b11);
    g_M[b * 6 + 2] = __fmaf_rn(a01, b12, __fmul_rn(a00, b02));
    g_M[b * 6 + 3] = __fmul_rn(a10, b00);
    g_M[b * 6 + 4] = __fmul_rn(a11, b11);
    g_M[b * 6 + 5] = __fmaf_rn(a11, b12, __fmul_rn(a10, b02));
}

extern __shared__ float buf[];   // TILES * TILE_FLOATS (48 KB dynamic)

__global__ __launch_bounds__(512) void aug_kernel(
    const float* __restrict__ img,
    float* __restrict__ out)
{
    const int rblk = blockIdx.x * (ROWS_PT * TILES);   // first row of this block
    const int b    = blockIdx.y;                       // image

    __shared__ float M[6];
    if (threadIdx.x < 6) M[threadIdx.x] = g_M[b * 6 + threadIdx.x];
    __syncthreads();

    const float m00 = M[0], m01 = M[1], m02 = M[2];
    const float m10 = M[3], m11 = M[4], m12 = M[5];

    const int c = threadIdx.x;                 // output col
    const float Y = (float)(c - DIM / 2);      // c - 256 (fixed per thread)
    const int img_base = b * (DIM * DIM * 3);  // fits in 32-bit

#pragma unroll
    for (int t = 0; t < TILES; t++) {
        const int r0 = rblk + t * ROWS_PT;
        float* tbuf = buf + t * TILE_FLOATS;

        // --- phase 1: 4 independent coordinate transforms (frozen numerics) ---
        int src[ROWS_PT];
#pragma unroll
        for (int i = 0; i < ROWS_PT; i++) {
            const int r = r0 + i;
            const float X = (float)(DIM / 2 - r);

            float fu = __fadd_rn(__fmaf_rn(m01, Y, __fmul_rn(m00, X)), m02);
            float fv = __fadd_rn(__fmaf_rn(m11, Y, __fmul_rn(m10, X)), m12);

            int iu = (int)fu;   // trunc toward zero == astype(int32)
            int iv = (int)fv;
            iu = min(max(iu, -(DIM / 2) + 1), DIM / 2);   // clip to [-255, 256]
            iv = min(max(iv, -(DIM / 2) + 1), DIM / 2);

            const int src_row = DIM / 2 - iu;        // [0, 511]
            const int src_col = DIM / 2 - 1 + iv;    // [0, 511]
            src[i] = img_base + (src_row * DIM + src_col) * 3;
        }

        // --- phase 2: 8 independent aligned LDG.64 (2 float2 per pixel) ---
        float2 qa[ROWS_PT], qb[ROWS_PT];
#pragma unroll
        for (int i = 0; i < ROWS_PT; i++) {
            const float2* f2p = (const float2*)(img + (src[i] & ~1));
            qa[i] = __ldg(f2p);
            qb[i] = __ldg(f2p + 1);
        }

        // --- phase 3: branchless parity select + stage into smem ---
#pragma unroll
        for (int i = 0; i < ROWS_PT; i++) {
            const bool odd = (src[i] & 1);
            float p0 = odd ? qa[i].y : qa[i].x;   // s
            float p1 = odd ? qb[i].x : qa[i].y;   // s+1
            float p2 = odd ? qb[i].y : qb[i].x;   // s+2
            const int base = i * (DIM * 3) + c * 3;   // stride-3: conflict-free
            tbuf[base + 0] = p0;
            tbuf[base + 1] = p1;
            tbuf[base + 2] = p2;
        }
        __syncthreads();

        // --- phase 4: issue TMA bulk store for this tile, do NOT wait ---
        if (threadIdx.x == 0) {
            float* dst = out + ((long long)(b * DIM + r0)) * (DIM * 3);
            uint32_t saddr;
            asm("{ .reg .u64 tt; cvta.to.shared.u64 tt, %1; cvt.u32.u64 %0, tt; }"
                : "=r"(saddr) : "l"(tbuf));
            asm volatile("fence.proxy.async.shared::cta;" ::: "memory");
            asm volatile(
                "cp.async.bulk.global.shared::cta.bulk_group [%0], [%1], %2;"
                :: "l"(dst), "r"(saddr), "n"(TILE_BYTES) : "memory");
            asm volatile("cp.async.bulk.commit_group;" ::: "memory");
        }
        // other threads fall through to next tile immediately (distinct buffer)
    }

    // --- drain both bulk stores before CTA exit (smem reuse safety) ---
    if (threadIdx.x == 0) {
        asm volatile("cp.async.bulk.wait_group 0;" ::: "memory");
    }
}

extern "C" void kernel_launch(void* const* d_in, const int* in_sizes, int n_in,
                              void* d_out, int out_size)
{
    const float* img = (const float*)d_in[0];
    const float* rot = (const float*)d_in[1];
    const float* shr = (const float*)d_in[2];
    const float* hz  = (const float*)d_in[3];
    const float* wz  = (const float*)d_in[4];
    const float* hs  = (const float*)d_in[5];
    const float* ws  = (const float*)d_in[6];
    float* out = (float*)d_out;

    cudaFuncSetAttribute(aug_kernel,
                         cudaFuncAttributeMaxDynamicSharedMemorySize, SMEM_BYTES);

    matrix_kernel<<<1, BATCH>>>(rot, shr, hz, wz, hs, ws);
    dim3 grid(DIM / (ROWS_PT * TILES), BATCH);
    aug_kernel<<<grid, DIM, SMEM_BYTES>>>(img, out);
}

// round 13
// speedup vs baseline: 1.5681x; 1.5681x over previous
#include <cuda_runtime.h>
#include <math.h>
#include <cstdint>

#define DIM 512
#define PI_F 3.14159265358979f   // rounds to 3.14159274f == f32(np.float64 PI)
#define BATCH 64
#define ROWS_PB 4                 // rows per block
#define COLS_PB 256               // cols per block
#define ROW_FLOATS (COLS_PB * 3)             // 768 floats = 3072 B per row slice
#define TILE_FLOATS (ROWS_PB * ROW_FLOATS)   // 3072 floats = 12 KB

// scratch for per-image matrices (allocation-free rule: __device__ global)
__device__ float g_M[BATCH * 6];

// ============================================================================
// Bit-exact replication of glibc (aarch64) sinf/cosf — numerics frozen (R6).
// ============================================================================

__device__ __constant__ double GSIGN[4] = {1.0, -1.0, -1.0, 1.0};

struct SCPoly { double c0, c1, c2, c3, c4, s1, s2, s3; };

__device__ __constant__ SCPoly GTAB[2] = {
    {  0x1p0,
      -0x1.ffffffd0c621cp-2,
       0x1.55553e1068f19p-5,
      -0x1.6c087e89a359dp-10,
       0x1.99343027bf8c3p-16,
      -0x1.555545995a603p-3,
       0x1.1107605230bc4p-7,
      -0x1.994eb3774cf24p-13 },
    { -0x1p0,
       0x1.ffffffd0c621cp-2,
      -0x1.55553e1068f19p-5,
       0x1.6c087e89a359dp-10,
      -0x1.99343027bf8c3p-16,
       0x1.555545995a603p-3,
      -0x1.1107605230bc4p-7,
       0x1.994eb3774cf24p-13 }
};

__device__ __constant__ double G_HPI_INV = 0x1.45F306DC9C883p-1;  // 2/pi
__device__ __constant__ double G_HPI     = 0x1.921FB54442D18p0;   // pi/2

__device__ __forceinline__ unsigned abstop12(float x) {
    return (__float_as_uint(x) >> 20) & 0x7ff;
}

__device__ __forceinline__ double g_sinf_poly(double x, double x2, const SCPoly* p, int n) {
    if ((n & 1) == 0) {
        double x3 = x * x2;
        double s1 = fma(x2, p->s3, p->s2);
        double x7 = x3 * x2;
        double s  = fma(x3, p->s1, x);
        return fma(x7, s1, s);
    } else {
        double x4 = x2 * x2;
        double c2 = fma(x2, p->c4, p->c3);
        double c1 = fma(x2, p->c1, p->c0);
        double x6 = x4 * x2;
        double c  = fma(x4, p->c2, c1);
        return fma(x6, c2, c);
    }
}

__device__ __forceinline__ double g_reduce_fast(double x, int* np) {
    double r = x * G_HPI_INV;
    *np = __double2int_rn(r);
    double rr = rint(r);
    return fma(rr, -G_HPI, x);
}

__device__ float glibc_sinf(float y) {
    unsigned t = abstop12(y);
    if (t < 0x3f4u) {
        double x = (double)y;
        double s = x * x;
        if (t < 0x398u)
            return y;
        return (float)g_sinf_poly(x, s, &GTAB[0], 0);
    } else {
        double x = (double)y;
        int n;
        x = g_reduce_fast(x, &n);
        double s = GSIGN[n & 3];
        const SCPoly* p = (n & 2) ? &GTAB[1] : &GTAB[0];
        return (float)g_sinf_poly(x * s, x * x, p, n);
    }
}

__device__ float glibc_cosf(float y) {
    unsigned t = abstop12(y);
    if (t < 0x3f4u) {
        double x = (double)y;
        double x2 = x * x;
        if (t < 0x398u)
            return 1.0f;
        return (float)g_sinf_poly(x, x2, &GTAB[0], 1);
    } else {
        double x = (double)y;
        int n;
        x = g_reduce_fast(x, &n);
        double s = GSIGN[(n + 1) & 3];
        const SCPoly* p = ((n + 1) & 2) ? &GTAB[1] : &GTAB[0];
        return (float)g_sinf_poly(x * s, x * x, p, n ^ 1);
    }
}

// ============================================================================

__global__ void matrix_kernel(
    const float* __restrict__ rot_n,
    const float* __restrict__ shr_n,
    const float* __restrict__ hz_n,
    const float* __restrict__ wz_n,
    const float* __restrict__ hs_n,
    const float* __restrict__ ws_n)
{
    const int b = threadIdx.x;
    if (b >= BATCH) return;

    float rotation = __fmul_rn(15.0f, rot_n[b]);
    float shear    = __fmul_rn(5.0f,  shr_n[b]);
    float h_zoom   = __fadd_rn(1.0f, __fdiv_rn(hz_n[b], 10.0f));
    float w_zoom   = __fadd_rn(1.0f, __fdiv_rn(wz_n[b], 10.0f));
    float h_shift  = __fmul_rn(16.0f, hs_n[b]);
    float w_shift  = __fmul_rn(16.0f, ws_n[b]);

    float rot = __fdiv_rn(__fmul_rn(PI_F, rotation), 180.0f);
    float shr = __fdiv_rn(__fmul_rn(PI_F, shear), 180.0f);
    float c1 = glibc_cosf(rot), s1 = glibc_sinf(rot);
    float c2 = glibc_cosf(shr), s2 = glibc_sinf(shr);

    // A = rot_m @ shear_m  (fma-ascending — frozen)
    float a00 = c1;
    float a01 = __fmaf_rn(s1, c2, __fmul_rn(c1, s2));
    float a10 = -s1;
    float a11 = __fmaf_rn(c1, c2, __fmul_rn(-s1, s2));

    // B = zoom_m @ shift_m
    float izh = __fdiv_rn(1.0f, h_zoom);
    float izw = __fdiv_rn(1.0f, w_zoom);
    float b00 = izh;
    float b02 = __fmul_rn(izh, h_shift);
    float b11 = izw;
    float b12 = __fmul_rn(izw, w_shift);

    // M = A @ B
    g_M[b * 6 + 0] = __fmul_rn(a00, b00);
    g_M[b * 6 + 1] = __fmul_rn(a01, b11);
    g_M[b * 6 + 2] = __fmaf_rn(a01, b12, __fmul_rn(a00, b02));
    g_M[b * 6 + 3] = __fmul_rn(a10, b00);
    g_M[b * 6 + 4] = __fmul_rn(a11, b11);
    g_M[b * 6 + 5] = __fmaf_rn(a11, b12, __fmul_rn(a10, b02));
}

__global__ __launch_bounds__(COLS_PB) void aug_kernel(
    const float* __restrict__ img,
    float* __restrict__ out)
{
    const int c0 = blockIdx.x * COLS_PB;   // first col of this block
    const int r0 = blockIdx.y * ROWS_PB;   // first row of this block
    const int b  = blockIdx.z;             // image

    __shared__ __align__(16) float buf[TILE_FLOATS];   // 12 KB staging

    // broadcast LDG of the 6 matrix coeffs (uniform address -> L1 broadcast,
    // no barrier needed)
    const float* Mb = g_M + b * 6;
    const float m00 = __ldg(Mb + 0), m01 = __ldg(Mb + 1), m02 = __ldg(Mb + 2);
    const float m10 = __ldg(Mb + 3), m11 = __ldg(Mb + 4), m12 = __ldg(Mb + 5);

    const int c = c0 + threadIdx.x;            // output col
    const float Y = (float)(c - DIM / 2);      // c - 256 (fixed per thread)
    const int img_base = b * (DIM * DIM * 3);  // fits in 32-bit

    // --- phase 1: 4 independent coordinate transforms (frozen R6 numerics) ---
    int src[ROWS_PB];
#pragma unroll
    for (int i = 0; i < ROWS_PB; i++) {
        const int r = r0 + i;
        const float X = (float)(DIM / 2 - r);

        float fu = __fadd_rn(__fmaf_rn(m01, Y, __fmul_rn(m00, X)), m02);
        float fv = __fadd_rn(__fmaf_rn(m11, Y, __fmul_rn(m10, X)), m12);

        int iu = (int)fu;   // trunc toward zero == astype(int32)
        int iv = (int)fv;
        iu = min(max(iu, -(DIM / 2) + 1), DIM / 2);   // clip to [-255, 256]
        iv = min(max(iv, -(DIM / 2) + 1), DIM / 2);

        const int src_row = DIM / 2 - iu;        // [0, 511]
        const int src_col = DIM / 2 - 1 + iv;    // [0, 511]
        src[i] = img_base + (src_row * DIM + src_col) * 3;
    }

    // --- phase 2: 8 independent aligned LDG.64 (2 float2 per pixel) ---
    float2 qa[ROWS_PB], qb[ROWS_PB];
#pragma unroll
    for (int i = 0; i < ROWS_PB; i++) {
        const float2* f2p = (const float2*)(img + (src[i] & ~1));
        qa[i] = __ldg(f2p);
        qb[i] = __ldg(f2p + 1);
    }

    // --- phase 3: branchless parity select + stage into smem ---
#pragma unroll
    for (int i = 0; i < ROWS_PB; i++) {
        const bool odd = (src[i] & 1);
        float p0 = odd ? qa[i].y : qa[i].x;   // s
        float p1 = odd ? qb[i].x : qa[i].y;   // s+1
        float p2 = odd ? qb[i].y : qb[i].x;   // s+2
        const int base = i * ROW_FLOATS + (int)threadIdx.x * 3;  // conflict-free
        buf[base + 0] = p0;
        buf[base + 1] = p1;
        buf[base + 2] = p2;
    }
    __syncthreads();

    // --- phase 4: per-row TMA bulk stores, issued by 4 different warps ---
    // threads 0,64,128,192 each store one 3 KB row slice and privately wait
    // until TMA has READ the smem (wait_group.read), not written gmem.
    if ((threadIdx.x & 63) == 0) {
        const int i = threadIdx.x >> 6;                 // row index 0..3
        float* dst = out + ((long long)(b * DIM + r0 + i)) * (DIM * 3) + c0 * 3;
        const float* srow = buf + i * ROW_FLOATS;
        uint32_t saddr;
        asm("{ .reg .u64 tt; cvta.to.shared.u64 tt, %1; cvt.u32.u64 %0, tt; }"
            : "=r"(saddr) : "l"(srow));
        asm volatile("fence.proxy.async.shared::cta;" ::: "memory");
        asm volatile(
            "cp.async.bulk.global.shared::cta.bulk_group [%0], [%1], %2;"
            :: "l"(dst), "r"(saddr), "n"(ROW_FLOATS * 4) : "memory");
        asm volatile("cp.async.bulk.commit_group;" ::: "memory");
        asm volatile("cp.async.bulk.wait_group.read 0;" ::: "memory");
    }
}

extern "C" void kernel_launch(void* const* d_in, const int* in_sizes, int n_in,
                              void* d_out, int out_size)
{
    const float* img = (const float*)d_in[0];
    const float* rot = (const float*)d_in[1];
    const float* shr = (const float*)d_in[2];
    const float* hz  = (const float*)d_in[3];
    const float* wz  = (const float*)d_in[4];
    const float* hs  = (const float*)d_in[5];
    const float* ws  = (const float*)d_in[6];
    float* out = (float*)d_out;

    matrix_kernel<<<1, BATCH>>>(rot, shr, hz, wz, hs, ws);
    dim3 grid(DIM / COLS_PB, DIM / ROWS_PB, BATCH);
    aug_kernel<<<grid, COLS_PB>>>(img, out);
}

// round 14
// speedup vs baseline: 1.5785x; 1.0066x over previous
#include <cuda_runtime.h>
#include <math.h>
#include <cstdint>

#define DIM 512
#define PI_F 3.14159265358979f   // rounds to 3.14159274f == f32(np.float64 PI)
#define BATCH 64
#define ROWS_PB 4                 // rows per block (== warps per block)
#define COLS_PB 128               // cols per block (== threads per block)
#define ROW_FLOATS (COLS_PB * 3)             // 384 floats = 1536 B per row slice
#define TILE_FLOATS (ROWS_PB * ROW_FLOATS)   // 1536 floats = 6 KB

// scratch for per-image matrices (allocation-free rule: __device__ global)
__device__ float g_M[BATCH * 6];

// ============================================================================
// Bit-exact replication of glibc (aarch64) sinf/cosf — numerics frozen (R6).
// ============================================================================

__device__ __constant__ double GSIGN[4] = {1.0, -1.0, -1.0, 1.0};

struct SCPoly { double c0, c1, c2, c3, c4, s1, s2, s3; };

__device__ __constant__ SCPoly GTAB[2] = {
    {  0x1p0,
      -0x1.ffffffd0c621cp-2,
       0x1.55553e1068f19p-5,
      -0x1.6c087e89a359dp-10,
       0x1.99343027bf8c3p-16,
      -0x1.555545995a603p-3,
       0x1.1107605230bc4p-7,
      -0x1.994eb3774cf24p-13 },
    { -0x1p0,
       0x1.ffffffd0c621cp-2,
      -0x1.55553e1068f19p-5,
       0x1.6c087e89a359dp-10,
      -0x1.99343027bf8c3p-16,
       0x1.555545995a603p-3,
      -0x1.1107605230bc4p-7,
       0x1.994eb3774cf24p-13 }
};

__device__ __constant__ double G_HPI_INV = 0x1.45F306DC9C883p-1;  // 2/pi
__device__ __constant__ double G_HPI     = 0x1.921FB54442D18p0;   // pi/2

__device__ __forceinline__ unsigned abstop12(float x) {
    return (__float_as_uint(x) >> 20) & 0x7ff;
}

__device__ __forceinline__ double g_sinf_poly(double x, double x2, const SCPoly* p, int n) {
    if ((n & 1) == 0) {
        double x3 = x * x2;
        double s1 = fma(x2, p->s3, p->s2);
        double x7 = x3 * x2;
        double s  = fma(x3, p->s1, x);
        return fma(x7, s1, s);
    } else {
        double x4 = x2 * x2;
        double c2 = fma(x2, p->c4, p->c3);
        double c1 = fma(x2, p->c1, p->c0);
        double x6 = x4 * x2;
        double c  = fma(x4, p->c2, c1);
        return fma(x6, c2, c);
    }
}

__device__ __forceinline__ double g_reduce_fast(double x, int* np) {
    double r = x * G_HPI_INV;
    *np = __double2int_rn(r);
    double rr = rint(r);
    return fma(rr, -G_HPI, x);
}

__device__ float glibc_sinf(float y) {
    unsigned t = abstop12(y);
    if (t < 0x3f4u) {
        double x = (double)y;
        double s = x * x;
        if (t < 0x398u)
            return y;
        return (float)g_sinf_poly(x, s, &GTAB[0], 0);
    } else {
        double x = (double)y;
        int n;
        x = g_reduce_fast(x, &n);
        double s = GSIGN[n & 3];
        const SCPoly* p = (n & 2) ? &GTAB[1] : &GTAB[0];
        return (float)g_sinf_poly(x * s, x * x, p, n);
    }
}

__device__ float glibc_cosf(float y) {
    unsigned t = abstop12(y);
    if (t < 0x3f4u) {
        double x = (double)y;
        double x2 = x * x;
        if (t < 0x398u)
            return 1.0f;
        return (float)g_sinf_poly(x, x2, &GTAB[0], 1);
    } else {
        double x = (double)y;
        int n;
        x = g_reduce_fast(x, &n);
        double s = GSIGN[(n + 1) & 3];
        const SCPoly* p = ((n + 1) & 2) ? &GTAB[1] : &GTAB[0];
        return (float)g_sinf_poly(x * s, x * x, p, n ^ 1);
    }
}

// ============================================================================

__global__ void matrix_kernel(
    const float* __restrict__ rot_n,
    const float* __restrict__ shr_n,
    const float* __restrict__ hz_n,
    const float* __restrict__ wz_n,
    const float* __restrict__ hs_n,
    const float* __restrict__ ws_n)
{
    const int b = threadIdx.x;
    if (b >= BATCH) return;

    float rotation = __fmul_rn(15.0f, rot_n[b]);
    float shear    = __fmul_rn(5.0f,  shr_n[b]);
    float h_zoom   = __fadd_rn(1.0f, __fdiv_rn(hz_n[b], 10.0f));
    float w_zoom   = __fadd_rn(1.0f, __fdiv_rn(wz_n[b], 10.0f));
    float h_shift  = __fmul_rn(16.0f, hs_n[b]);
    float w_shift  = __fmul_rn(16.0f, ws_n[b]);

    float rot = __fdiv_rn(__fmul_rn(PI_F, rotation), 180.0f);
    float shr = __fdiv_rn(__fmul_rn(PI_F, shear), 180.0f);
    float c1 = glibc_cosf(rot), s1 = glibc_sinf(rot);
    float c2 = glibc_cosf(shr), s2 = glibc_sinf(shr);

    // A = rot_m @ shear_m  (fma-ascending — frozen)
    float a00 = c1;
    float a01 = __fmaf_rn(s1, c2, __fmul_rn(c1, s2));
    float a10 = -s1;
    float a11 = __fmaf_rn(c1, c2, __fmul_rn(-s1, s2));

    // B = zoom_m @ shift_m
    float izh = __fdiv_rn(1.0f, h_zoom);
    float izw = __fdiv_rn(1.0f, w_zoom);
    float b00 = izh;
    float b02 = __fmul_rn(izh, h_shift);
    float b11 = izw;
    float b12 = __fmul_rn(izw, w_shift);

    // M = A @ B
    g_M[b * 6 + 0] = __fmul_rn(a00, b00);
    g_M[b * 6 + 1] = __fmul_rn(a01, b11);
    g_M[b * 6 + 2] = __fmaf_rn(a01, b12, __fmul_rn(a00, b02));
    g_M[b * 6 + 3] = __fmul_rn(a10, b00);
    g_M[b * 6 + 4] = __fmul_rn(a11, b11);
    g_M[b * 6 + 5] = __fmaf_rn(a11, b12, __fmul_rn(a10, b02));
}

__global__ __launch_bounds__(COLS_PB) void aug_kernel(
    const float* __restrict__ img,
    float* __restrict__ out)
{
    const int c0 = blockIdx.x * COLS_PB;   // first col of this block
    const int r0 = blockIdx.y * ROWS_PB;   // first row of this block
    const int b  = blockIdx.z;             // image

    __shared__ __align__(16) float buf[TILE_FLOATS];   // 6 KB staging

    // broadcast LDG of the 6 matrix coeffs (uniform address -> L1 broadcast)
    const float* Mb = g_M + b * 6;
    const float m00 = __ldg(Mb + 0), m01 = __ldg(Mb + 1), m02 = __ldg(Mb + 2);
    const float m10 = __ldg(Mb + 3), m11 = __ldg(Mb + 4), m12 = __ldg(Mb + 5);

    const int c = c0 + threadIdx.x;            // output col
    const float Y = (float)(c - DIM / 2);      // c - 256 (fixed per thread)
    const int img_base = b * (DIM * DIM * 3);  // fits in 32-bit

    // --- phase 1: 4 independent coordinate transforms (frozen R6 numerics) ---
    int src[ROWS_PB];
#pragma unroll
    for (int i = 0; i < ROWS_PB; i++) {
        const int r = r0 + i;
        const float X = (float)(DIM / 2 - r);

        float fu = __fadd_rn(__fmaf_rn(m01, Y, __fmul_rn(m00, X)), m02);
        float fv = __fadd_rn(__fmaf_rn(m11, Y, __fmul_rn(m10, X)), m12);

        int iu = (int)fu;   // trunc toward zero == astype(int32)
        int iv = (int)fv;
        iu = min(max(iu, -(DIM / 2) + 1), DIM / 2);   // clip to [-255, 256]
        iv = min(max(iv, -(DIM / 2) + 1), DIM / 2);

        const int src_row = DIM / 2 - iu;        // [0, 511]
        const int src_col = DIM / 2 - 1 + iv;    // [0, 511]
        src[i] = img_base + (src_row * DIM + src_col) * 3;
    }

    // --- phase 2: 8 independent aligned LDG.64 (2 float2 per pixel) ---
    float2 qa[ROWS_PB], qb[ROWS_PB];
#pragma unroll
    for (int i = 0; i < ROWS_PB; i++) {
        const float2* f2p = (const float2*)(img + (src[i] & ~1));
        qa[i] = __ldg(f2p);
        qb[i] = __ldg(f2p + 1);
    }

    // --- phase 3: branchless parity select + stage into smem ---
#pragma unroll
    for (int i = 0; i < ROWS_PB; i++) {
        const bool odd = (src[i] & 1);
        float p0 = odd ? qa[i].y : qa[i].x;   // s
        float p1 = odd ? qb[i].x : qa[i].y;   // s+1
        float p2 = odd ? qb[i].y : qb[i].x;   // s+2
        const int base = i * ROW_FLOATS + (int)threadIdx.x * 3;  // conflict-free
        buf[base + 0] = p0;
        buf[base + 1] = p1;
        buf[base + 2] = p2;
    }
    __syncthreads();   // spans only 4 warps

    // --- phase 4: per-row TMA bulk stores, warp i stores row i ---
    if ((threadIdx.x & 31) == 0) {
        const int i = threadIdx.x >> 5;                 // warp id == row index
        float* dst = out + ((long long)(b * DIM + r0 + i)) * (DIM * 3) + c0 * 3;
        const float* srow = buf + i * ROW_FLOATS;
        uint32_t saddr;
        asm("{ .reg .u64 tt; cvta.to.shared.u64 tt, %1; cvt.u32.u64 %0, tt; }"
            : "=r"(saddr) : "l"(srow));
        asm volatile("fence.proxy.async.shared::cta;" ::: "memory");
        asm volatile(
            "cp.async.bulk.global.shared::cta.bulk_group [%0], [%1], %2;"
            :: "l"(dst), "r"(saddr), "n"(ROW_FLOATS * 4) : "memory");
        asm volatile("cp.async.bulk.commit_group;" ::: "memory");
        asm volatile("cp.async.bulk.wait_group.read 0;" ::: "memory");
    }
}

extern "C" void kernel_launch(void* const* d_in, const int* in_sizes, int n_in,
                              void* d_out, int out_size)
{
    const float* img = (const float*)d_in[0];
    const float* rot = (const float*)d_in[1];
    const float* shr = (const float*)d_in[2];
    const float* hz  = (const float*)d_in[3];
    const float* wz  = (const float*)d_in[4];
    const float* hs  = (const float*)d_in[5];
    const float* ws  = (const float*)d_in[6];
    float* out = (float*)d_out;

    matrix_kernel<<<1, BATCH>>>(rot, shr, hz, wz, hs, ws);
    dim3 grid(DIM / COLS_PB, DIM / ROWS_PB, BATCH);
    aug_kernel<<<grid, COLS_PB>>>(img, out);
}